// round 4
// baseline (speedup 1.0000x reference)
#include <cuda_runtime.h>

// Problem constants
#define B_N   16
#define LATD  512
#define FIN   128
#define FOUT  128
#define HH    64
#define WWC   64
#define KSZ   147456        // FOUT*FIN*3*3
#define JTOT  147584        // KSZ + FOUT

// Conv tiling
#define CO_T  64
#define TH    8
#define TW    32
#define CI_T  8

// Scratch for the generated per-sample kernels + biases (9.4 MB)
__device__ float g_ks[(size_t)B_N * JTOT];

typedef unsigned long long ull;

__device__ __forceinline__ ull pack2(float lo, float hi) {
    ull r;
    asm("mov.b64 %0, {%1, %2};" : "=l"(r) : "f"(lo), "f"(hi));
    return r;
}
__device__ __forceinline__ void unpack2(ull v, float &lo, float &hi) {
    asm("mov.b64 {%0, %1}, %2;" : "=f"(lo), "=f"(hi) : "l"(v));
}
// packed dual-lane fp32 FMA (sm_103a): d = a*b + d, lanewise on 2xf32
__device__ __forceinline__ void ffma2(ull &d, ull a, ull b) {
    asm("fma.rn.f32x2 %0, %1, %2, %0;" : "+l"(d) : "l"(a), "l"(b));
}

// ---------------------------------------------------------------------------
// Kernel 1: ks[b][j] = sum_l lat[b][l] * W[j][l] + bias[j]
// One thread per j; lat (16x512) staged in smem, broadcast reads.
// W rows streamed via float4 (full 128B line consumption via L1 temporal reuse).
// ---------------------------------------------------------------------------
__global__ void __launch_bounds__(256) ks_gemm_kernel(const float* __restrict__ lat,
                                                      const float* __restrict__ W,
                                                      const float* __restrict__ bias) {
    __shared__ float4 lat_s[B_N * (LATD / 4)];   // 2048 float4 = 32 KB
    const int tid = threadIdx.x;
    const float4* lat4 = reinterpret_cast<const float4*>(lat);
    for (int i = tid; i < B_N * (LATD / 4); i += 256) lat_s[i] = lat4[i];
    __syncthreads();

    const int j = blockIdx.x * 256 + tid;
    if (j >= JTOT) return;

    float acc[B_N];
#pragma unroll
    for (int b = 0; b < B_N; b++) acc[b] = 0.f;

    const float4* Wr = reinterpret_cast<const float4*>(W + (size_t)j * LATD);
#pragma unroll 2
    for (int kk = 0; kk < LATD / 4; kk++) {
        const float4 w = Wr[kk];
#pragma unroll
        for (int b = 0; b < B_N; b++) {
            const float4 l = lat_s[b * (LATD / 4) + kk];
            acc[b] += w.x * l.x + w.y * l.y + w.z * l.z + w.w * l.w;
        }
    }
    const float bj = bias[j];
#pragma unroll
    for (int b = 0; b < B_N; b++)
        g_ks[(size_t)b * JTOT + j] = acc[b] + bj;
}

// ---------------------------------------------------------------------------
// Kernel 2: per-sample 3x3 conv with the generated kernels.
// Grid: x = 16 spatial tiles (8 row-tiles x 2 col-tiles), y = co tile (2), z = b (16).
// Block: 256 threads. Thread = 8 output channels (4 packed co-pairs) x 8 rows x 1 col.
// Inner loop on packed fma.rn.f32x2 over co-pairs; kern smem is pair-interleaved
// so each co-pair load is a single LDS.64 broadcast.
// ---------------------------------------------------------------------------
__global__ void __launch_bounds__(256, 2) dynconv_kernel(const float* __restrict__ x,
                                                         float* __restrict__ y) {
    __shared__ float x_s[CI_T * 10 * 36];            // 2880 floats (pitch 36)
    __shared__ float k_s[(CO_T / 2) * 72 * 2];       // 4608 floats, pair-interleaved

    const int tid     = threadIdx.x;
    const int b       = blockIdx.z;
    const int co_base = blockIdx.y * CO_T;
    const int sp      = blockIdx.x;                  // 0..15
    const int r0      = (sp >> 1) * TH;
    const int c0      = (sp & 1) * TW;
    const int tcol    = tid & 31;
    const int cg      = tid >> 5;                    // warp id = co-group (0..7)

    const float* kb = g_ks + (size_t)b * JTOT;

    ull acc[4][8];
#pragma unroll
    for (int p = 0; p < 4; p++)
#pragma unroll
        for (int r = 0; r < 8; r++) acc[p][r] = 0ULL;

    for (int cic = 0; cic < FIN / CI_T; cic++) {
        // ---- stage x tile (CI_T channels, 10 rows x 34 cols with halo, zero-padded)
        const float* xb = x + ((size_t)b * FIN + cic * CI_T) * (HH * WWC);
        for (int idx = tid; idx < CI_T * 10 * 34; idx += 256) {
            const int ci  = idx / 340;
            const int rem = idx - ci * 340;
            const int r   = rem / 34;
            const int c   = rem - r * 34;
            const int gr  = r0 + r - 1;
            const int gc  = c0 + c - 1;
            float v = 0.f;
            if (gr >= 0 && gr < HH && gc >= 0 && gc < WWC)
                v = xb[ci * (HH * WWC) + gr * WWC + gc];
            x_s[ci * 360 + r * 36 + c] = v;
        }
        // ---- stage kern tile (64 co x 8 ci x 9 taps), pair-interleaved over co
        for (int idx = tid; idx < CO_T * 72; idx += 256) {
            const int co_l = idx / 72;
            const int rr   = idx - co_l * 72;        // ci_l*9 + kk
            const float v  = kb[(size_t)(co_base + co_l) * 1152 + cic * 72 + rr];
            k_s[((co_l >> 1) * 72 + rr) * 2 + (co_l & 1)] = v;
        }
        __syncthreads();

        // ---- compute
#pragma unroll 1
        for (int ci = 0; ci < CI_T; ci++) {
            const float* xr = &x_s[ci * 360];
            const float* kr = &k_s[(cg * 4) * 72 * 2 + ci * 9 * 2];
#pragma unroll
            for (int kw = 0; kw < 3; kw++) {
                ull xd[10];
#pragma unroll
                for (int r = 0; r < 10; r++) {
                    const float v = xr[r * 36 + tcol + kw];
                    xd[r] = pack2(v, v);
                }
#pragma unroll
                for (int kh = 0; kh < 3; kh++) {
#pragma unroll
                    for (int pi = 0; pi < 4; pi++) {
                        const int pidx = pi * 72 * 2 + (kh * 3 + kw) * 2;
                        const ull kv = pack2(kr[pidx], kr[pidx + 1]);
#pragma unroll
                        for (int r = 0; r < 8; r++)
                            ffma2(acc[pi][r], kv, xd[r + kh]);
                    }
                }
            }
        }
        __syncthreads();
    }

    // ---- epilogue: unpack, add generated bias, store
#pragma unroll
    for (int pi = 0; pi < 4; pi++) {
        const int co0 = co_base + cg * 8 + 2 * pi;
        const float b0 = kb[KSZ + co0];
        const float b1 = kb[KSZ + co0 + 1];
#pragma unroll
        for (int r = 0; r < 8; r++) {
            float lo, hi;
            unpack2(acc[pi][r], lo, hi);
            const int gr = r0 + r;
            const int gc = c0 + tcol;
            y[(((size_t)b * FOUT + co0) * HH + gr) * WWC + gc]       = lo + b0;
            y[(((size_t)b * FOUT + co0 + 1) * HH + gr) * WWC + gc]   = hi + b1;
        }
    }
}

// ---------------------------------------------------------------------------
// Inputs (metadata order): x (16,128,64,64) f32 | lat (16,512) f32
//                          W (147584,512) f32   | b (147584,) f32
// Output: (16,128,64,64) f32
// ---------------------------------------------------------------------------
extern "C" void kernel_launch(void* const* d_in, const int* in_sizes, int n_in,
                              void* d_out, int out_size) {
    const float* x    = (const float*)d_in[0];
    const float* lat  = (const float*)d_in[1];
    const float* W    = (const float*)d_in[2];
    const float* bias = (const float*)d_in[3];
    float* y = (float*)d_out;

    const int gemm_blocks = (JTOT + 255) / 256;
    ks_gemm_kernel<<<gemm_blocks, 256>>>(lat, W, bias);

    dim3 grid(16, FOUT / CO_T, B_N);
    dynconv_kernel<<<grid, 256>>>(x, y);
}

// round 6
// speedup vs baseline: 1.7757x; 1.7757x over previous
#include <cuda_runtime.h>
#include <cuda_fp16.h>
#include <cstdint>

#define B_N   16
#define LATD  512
#define KSZ   147456
#define JTOT  147584

// ---------------- persistent scratch ----------------
__device__ float   g_ks[(size_t)B_N * JTOT];
__device__ __half  g_kh[(size_t)B_N * 9 * 128 * 128];   // [b][tap][co][ci] fp16 hi
__device__ __half  g_kl[(size_t)B_N * 9 * 128 * 128];   // lo
__device__ __half  g_xh[(size_t)B_N * 66 * 66 * 128];   // [b][pr][pc][ci], zero border
__device__ __half  g_xl[(size_t)B_N * 66 * 66 * 128];

// ---------------- helpers ----------------
__device__ __forceinline__ uint32_t smem_u32(const void* p) {
    uint32_t a;
    asm("{ .reg .u64 t; cvta.to.shared.u64 t, %1; cvt.u32.u64 %0, t; }" : "=r"(a) : "l"(p));
    return a;
}
__device__ __forceinline__ void ldm4(uint32_t* r, uint32_t addr) {
    asm volatile("ldmatrix.sync.aligned.m8n8.x4.shared.b16 {%0,%1,%2,%3}, [%4];"
                 : "=r"(r[0]), "=r"(r[1]), "=r"(r[2]), "=r"(r[3]) : "r"(addr));
}
__device__ __forceinline__ void mma16816(float* c, const uint32_t* a, uint32_t b0, uint32_t b1) {
    asm volatile("mma.sync.aligned.m16n8k16.row.col.f32.f16.f16.f32 "
                 "{%0,%1,%2,%3}, {%4,%5,%6,%7}, {%8,%9}, {%0,%1,%2,%3};"
                 : "+f"(c[0]), "+f"(c[1]), "+f"(c[2]), "+f"(c[3])
                 : "r"(a[0]), "r"(a[1]), "r"(a[2]), "r"(a[3]), "r"(b0), "r"(b1));
}

// ---------------- kernel 1: ks = lat @ W.T + b (fp32, HBM-bound) ----------------
__global__ void __launch_bounds__(256) ks_gemm_kernel(const float* __restrict__ lat,
                                                      const float* __restrict__ W,
                                                      const float* __restrict__ bias) {
    __shared__ float4 lat_s[B_N * (LATD / 4)];
    const int tid = threadIdx.x;
    const float4* lat4 = reinterpret_cast<const float4*>(lat);
    for (int i = tid; i < B_N * (LATD / 4); i += 256) lat_s[i] = lat4[i];
    __syncthreads();
    const int j = blockIdx.x * 256 + tid;
    if (j >= JTOT) return;
    float acc[B_N];
#pragma unroll
    for (int b = 0; b < B_N; b++) acc[b] = 0.f;
    const float4* Wr = reinterpret_cast<const float4*>(W + (size_t)j * LATD);
#pragma unroll 2
    for (int kk = 0; kk < LATD / 4; kk++) {
        const float4 w = Wr[kk];
#pragma unroll
        for (int b = 0; b < B_N; b++) {
            const float4 l = lat_s[b * (LATD / 4) + kk];
            acc[b] += w.x * l.x + w.y * l.y + w.z * l.z + w.w * l.w;
        }
    }
    const float bj = bias[j];
#pragma unroll
    for (int b = 0; b < B_N; b++)
        g_ks[(size_t)b * JTOT + j] = acc[b] + bj;
}

// ---------------- kernel 2: split kern -> [b][tap][co][ci] fp16 hi/lo ----------------
__global__ void __launch_bounds__(256) ksplit_kernel() {
    const size_t N = (size_t)B_N * 9 * 128 * 128;
    size_t i = (size_t)blockIdx.x * 256 + threadIdx.x;
    if (i >= N) return;
    int ci  = (int)(i & 127);
    int co  = (int)((i >> 7) & 127);
    int tap = (int)((i >> 14) % 9);
    int b   = (int)((i >> 14) / 9);
    float v = g_ks[(size_t)b * JTOT + ((size_t)co * 128 + ci) * 9 + tap];
    __half h = __float2half(v);
    g_kh[i] = h;
    g_kl[i] = __float2half(v - __half2float(h));
}

// ---------------- kernel 3: transpose+split x -> padded [b][pr][pc][ci] fp16 ----------------
__global__ void __launch_bounds__(256) xsplit_kernel(const float* __restrict__ x) {
    __shared__ float s[128 * 65];
    const int b = blockIdx.y, r = blockIdx.x, t = threadIdx.x;
    const float* xb = x + (size_t)b * 128 * 4096 + (size_t)r * 64;
    for (int i = t; i < 128 * 64; i += 256) {
        int ci = i >> 6, c = i & 63;
        s[ci * 65 + c] = xb[(size_t)ci * 4096 + c];
    }
    __syncthreads();
    size_t obase = ((size_t)b * 66 + (r + 1)) * 66 * 128 + 128;   // pc starts at 1
    for (int i = t; i < 128 * 64; i += 256) {
        int c = i >> 7, ci = i & 127;
        float v = s[ci * 65 + c];
        __half h = __float2half(v);
        g_xh[obase + (size_t)c * 128 + ci] = h;
        g_xl[obase + (size_t)c * 128 + ci] = __float2half(v - __half2float(h));
    }
}

// ---------------- kernel 4: HMMA conv ----------------
// CTA: 128 co x (2 rows x 64 cols). 8 warps = 2 co-groups x 4 pos-groups (warp: 64co x 32pos).
// 12 stages: kh(3) x ci-chunk-32(4). smem pitch 40 halves -> conflict-free ldmatrix.
#define A_TILE   5120              // 128 * 40 halves per (kw,hl) tile
#define A_ELEMS  (6 * A_TILE)      // 30720
#define B_ROW    (66 * 40)         // 2640 halves per (hl,rr)
#define B_ELEMS  (4 * B_ROW)       // 10560
#define SMEM_BYTES ((A_ELEMS + B_ELEMS) * 2)   // 82560

__global__ void __launch_bounds__(256, 2) conv_mma_kernel(float* __restrict__ y) {
    extern __shared__ __half sm[];
    __half* As = sm;
    __half* Bs = sm + A_ELEMS;
    const uint32_t as_u = smem_u32(As);
    const uint32_t bs_u = smem_u32(Bs);

    const int t = threadIdx.x, lane = t & 31, w = t >> 5;
    const int b = blockIdx.y, q = blockIdx.x;
    const int cog = w >> 2, posg = w & 3;
    const int rr_w = posg >> 1, c0w = (posg & 1) * 32;

    const int a_mrow = lane & 15;
    const int a_koff = (lane >= 16) ? 8 : 0;
    const int b_nrow = (lane & 7) + ((lane >= 16) ? 8 : 0);
    const int b_koff = ((lane >> 3) & 1) * 8;

    float acc[4][4][4];
#pragma unroll
    for (int mf = 0; mf < 4; mf++)
#pragma unroll
        for (int nf = 0; nf < 4; nf++)
#pragma unroll
            for (int e = 0; e < 4; e++) acc[mf][nf][e] = 0.f;

    for (int kh = 0; kh < 3; kh++) {
        for (int cch = 0; cch < 4; cch++) {
            // ---- stage A: 3 kw x 2 hl x 128 co x 32 ci  (3072 uint4)
#pragma unroll
            for (int i = 0; i < 12; i++) {
                int idx  = t + i * 256;
                int u    = idx & 3;
                int co   = (idx >> 2) & 127;
                int kwhl = idx >> 9;               // 0..5 = hl*3+kw
                int kw   = kwhl % 3, hl = kwhl / 3;
                const __half* src = (hl ? g_kl : g_kh)
                    + ((size_t)(b * 9 + kh * 3 + kw) * 16384 + (size_t)co * 128 + cch * 32 + u * 8);
                uint4 v = *reinterpret_cast<const uint4*>(src);
                *reinterpret_cast<uint4*>(As + (size_t)kwhl * A_TILE + co * 40 + u * 8) = v;
            }
            // ---- stage B: 2 hl x 2 rr x 66 pc x 32 ci  (1056 uint4)
#pragma unroll
            for (int i = 0; i < 5; i++) {
                int idx = t + i * 256;
                if (idx < 1056) {
                    int u    = idx & 3;
                    int pc   = (idx >> 2) % 66;
                    int rrhl = (idx >> 2) / 66;    // 0..3 = hl*2+rr
                    int rr = rrhl & 1, hl = rrhl >> 1;
                    const __half* src = (hl ? g_xl : g_xh)
                        + (((size_t)b * 66 + (q * 2 + rr + kh)) * 66 + pc) * 128 + cch * 32 + u * 8;
                    uint4 v = *reinterpret_cast<const uint4*>(src);
                    *reinterpret_cast<uint4*>(Bs + (size_t)rrhl * B_ROW + pc * 40 + u * 8) = v;
                }
            }
            __syncthreads();

            // ---- compute
#pragma unroll
            for (int kw = 0; kw < 3; kw++) {
#pragma unroll
                for (int k16 = 0; k16 < 2; k16++) {
                    const int k0 = k16 * 16;
                    uint32_t Bh[8], Bl[8];
#pragma unroll
                    for (int p = 0; p < 2; p++) {
                        uint32_t ah = bs_u +
                            (((0 * 2 + rr_w) * 66 + c0w + p * 16 + b_nrow + kw) * 40 + k0 + b_koff) * 2;
                        ldm4(&Bh[p * 4], ah);
                        ldm4(&Bl[p * 4], ah + 2 * B_ROW * 2);
                    }
#pragma unroll
                    for (int mf = 0; mf < 4; mf++) {
                        uint32_t Ah[4], Al[4];
                        uint32_t aa = as_u +
                            ((uint32_t)kw * A_TILE + (cog * 64 + mf * 16 + a_mrow) * 40 + k0 + a_koff) * 2;
                        ldm4(Ah, aa);
                        ldm4(Al, aa + 3 * A_TILE * 2);
#pragma unroll
                        for (int nf = 0; nf < 4; nf++) {
                            const int bi = (nf >> 1) * 4 + (nf & 1) * 2;
                            mma16816(acc[mf][nf], Ah, Bh[bi], Bh[bi + 1]);
                            mma16816(acc[mf][nf], Ah, Bl[bi], Bl[bi + 1]);
                            mma16816(acc[mf][nf], Al, Bh[bi], Bh[bi + 1]);
                        }
                    }
                }
            }
            __syncthreads();
        }
    }

    // ---- epilogue: add generated bias, store fp32
    const int row_g = q * 2 + rr_w;
#pragma unroll
    for (int mf = 0; mf < 4; mf++) {
        const int co_a = cog * 64 + mf * 16 + (lane >> 2);
        const float bv0 = g_ks[(size_t)b * JTOT + KSZ + co_a];
        const float bv1 = g_ks[(size_t)b * JTOT + KSZ + co_a + 8];
        float* base0 = y + (((size_t)b * 128 + co_a) * 64 + row_g) * 64;
        float* base1 = y + (((size_t)b * 128 + co_a + 8) * 64 + row_g) * 64;
#pragma unroll
        for (int nf = 0; nf < 4; nf++) {
            const int col = c0w + nf * 8 + (lane & 3) * 2;
            float2 v0 = make_float2(acc[mf][nf][0] + bv0, acc[mf][nf][1] + bv0);
            float2 v1 = make_float2(acc[mf][nf][2] + bv1, acc[mf][nf][3] + bv1);
            *reinterpret_cast<float2*>(base0 + col) = v0;
            *reinterpret_cast<float2*>(base1 + col) = v1;
        }
    }
}

// ---------------- launch ----------------
extern "C" void kernel_launch(void* const* d_in, const int* in_sizes, int n_in,
                              void* d_out, int out_size) {
    const float* x    = (const float*)d_in[0];
    const float* lat  = (const float*)d_in[1];
    const float* W    = (const float*)d_in[2];
    const float* bias = (const float*)d_in[3];
    float* y = (float*)d_out;

    cudaFuncSetAttribute(conv_mma_kernel, cudaFuncAttributeMaxDynamicSharedMemorySize, SMEM_BYTES);

    ks_gemm_kernel<<<(JTOT + 255) / 256, 256>>>(lat, W, bias);
    ksplit_kernel<<<(int)(((size_t)B_N * 9 * 128 * 128 + 255) / 256), 256>>>();
    xsplit_kernel<<<dim3(64, B_N), 256>>>(x);
    conv_mma_kernel<<<dim3(32, B_N), 256, SMEM_BYTES>>>(y);
}

// round 8
// speedup vs baseline: 2.3809x; 1.3408x over previous
#include <cuda_runtime.h>
#include <cuda_fp16.h>
#include <cstdint>

#define B_N   16
#define LATD  512
#define KSZ   147456
#define JTOT  147584

typedef unsigned long long ull;

// ---------------- persistent scratch ----------------
__device__ float   g_ks[(size_t)B_N * JTOT];
__device__ __half  g_k [(size_t)B_N * 9 * 128 * 128];   // [b][tap][co][ci] fp16 (single)
__device__ __half  g_xh[(size_t)B_N * 66 * 66 * 128];   // [b][pr][pc][ci] hi, zero border
__device__ __half  g_xl[(size_t)B_N * 66 * 66 * 128];   // lo

// ---------------- helpers ----------------
__device__ __forceinline__ uint32_t smem_u32(const void* p) {
    uint32_t a;
    asm("{ .reg .u64 t; cvta.to.shared.u64 t, %1; cvt.u32.u64 %0, t; }" : "=r"(a) : "l"(p));
    return a;
}
__device__ __forceinline__ void ldm4(uint32_t* r, uint32_t addr) {
    asm volatile("ldmatrix.sync.aligned.m8n8.x4.shared.b16 {%0,%1,%2,%3}, [%4];"
                 : "=r"(r[0]), "=r"(r[1]), "=r"(r[2]), "=r"(r[3]) : "r"(addr));
}
__device__ __forceinline__ void mma16816(float* c, const uint32_t* a, uint32_t b0, uint32_t b1) {
    asm volatile("mma.sync.aligned.m16n8k16.row.col.f32.f16.f16.f32 "
                 "{%0,%1,%2,%3}, {%4,%5,%6,%7}, {%8,%9}, {%0,%1,%2,%3};"
                 : "+f"(c[0]), "+f"(c[1]), "+f"(c[2]), "+f"(c[3])
                 : "r"(a[0]), "r"(a[1]), "r"(a[2]), "r"(a[3]), "r"(b0), "r"(b1));
}
__device__ __forceinline__ void cpa16(uint32_t d, const void* s) {
    asm volatile("cp.async.ca.shared.global [%0], [%1], 16;" :: "r"(d), "l"(s));
}
__device__ __forceinline__ ull pack2(float lo, float hi) {
    ull r; asm("mov.b64 %0, {%1, %2};" : "=l"(r) : "f"(lo), "f"(hi)); return r;
}
__device__ __forceinline__ void unpack2(ull v, float& lo, float& hi) {
    asm("mov.b64 {%0, %1}, %2;" : "=f"(lo), "=f"(hi) : "l"(v));
}
__device__ __forceinline__ void ffma2(ull& d, ull a, ull b) {
    asm("fma.rn.f32x2 %0, %1, %2, %0;" : "+l"(d) : "l"(a), "l"(b));
}

// ---------------- kernel 1: ks = lat @ W.T + b, packed f32x2 over batch pairs ----------------
__global__ void __launch_bounds__(256) ks_gemm_kernel(const float* __restrict__ lat,
                                                      const float* __restrict__ W,
                                                      const float* __restrict__ bias) {
    __shared__ ull lat2[8 * LATD];   // 32 KB
    const int tid = threadIdx.x;
    for (int i = tid; i < 8 * LATD; i += 256) {
        const int bp = i >> 9, k = i & 511;
        lat2[i] = pack2(lat[(2 * bp) * LATD + k], lat[(2 * bp + 1) * LATD + k]);
    }
    __syncthreads();

    const int j0 = blockIdx.x * 512 + tid;
    const int j1 = j0 + 256;
    const int j0c = (j0 < JTOT) ? j0 : (JTOT - 1);
    const int j1c = (j1 < JTOT) ? j1 : (JTOT - 1);

    ull a0[8], a1[8];
#pragma unroll
    for (int bp = 0; bp < 8; bp++) { a0[bp] = 0ULL; a1[bp] = 0ULL; }

    const float4* W0 = reinterpret_cast<const float4*>(W + (size_t)j0c * LATD);
    const float4* W1 = reinterpret_cast<const float4*>(W + (size_t)j1c * LATD);

#pragma unroll 2
    for (int kk = 0; kk < LATD / 4; kk++) {
        const float4 wa = W0[kk];
        const float4 wb = W1[kk];
        const float wav[4] = {wa.x, wa.y, wa.z, wa.w};
        const float wbv[4] = {wb.x, wb.y, wb.z, wb.w};
#pragma unroll
        for (int e = 0; e < 4; e++) {
            const ull w0 = pack2(wav[e], wav[e]);
            const ull w1 = pack2(wbv[e], wbv[e]);
            const int k = kk * 4 + e;
#pragma unroll
            for (int bp = 0; bp < 8; bp++) {
                const ull l = lat2[bp * LATD + k];
                ffma2(a0[bp], w0, l);
                ffma2(a1[bp], w1, l);
            }
        }
    }

    const float bj0 = bias[j0c];
    const float bj1 = bias[j1c];
#pragma unroll
    for (int bp = 0; bp < 8; bp++) {
        float lo, hi;
        if (j0 < JTOT) {
            unpack2(a0[bp], lo, hi);
            g_ks[(size_t)(2 * bp) * JTOT + j0]     = lo + bj0;
            g_ks[(size_t)(2 * bp + 1) * JTOT + j0] = hi + bj0;
        }
        if (j1 < JTOT) {
            unpack2(a1[bp], lo, hi);
            g_ks[(size_t)(2 * bp) * JTOT + j1]     = lo + bj1;
            g_ks[(size_t)(2 * bp + 1) * JTOT + j1] = hi + bj1;
        }
    }
}

// ---------------- kernel 2: convert kern -> [b][tap][co][ci] fp16 ----------------
__global__ void __launch_bounds__(256) kcvt_kernel() {
    const size_t N = (size_t)B_N * 9 * 128 * 128;
    size_t i = (size_t)blockIdx.x * 256 + threadIdx.x;
    if (i >= N) return;
    int ci  = (int)(i & 127);
    int co  = (int)((i >> 7) & 127);
    int tap = (int)((i >> 14) % 9);
    int b   = (int)((i >> 14) / 9);
    g_k[i] = __float2half(g_ks[(size_t)b * JTOT + ((size_t)co * 128 + ci) * 9 + tap]);
}

// ---------------- kernel 3: transpose + hi/lo split x -> padded [b][pr][pc][ci] ----------------
__global__ void __launch_bounds__(256) xsplit_kernel(const float* __restrict__ x) {
    __shared__ float s[128 * 65];
    const int b = blockIdx.y, r = blockIdx.x, t = threadIdx.x;
    const float* xb = x + (size_t)b * 128 * 4096 + (size_t)r * 64;
    for (int i = t; i < 128 * 64; i += 256) {
        int ci = i >> 6, c = i & 63;
        s[ci * 65 + c] = xb[(size_t)ci * 4096 + c];
    }
    __syncthreads();
    size_t obase = ((size_t)b * 66 + (r + 1)) * 66 * 128 + 128;
    for (int i = t; i < 128 * 64; i += 256) {
        int c = i >> 7, ci = i & 127;
        float v = s[ci * 65 + c];
        __half h = __float2half(v);
        g_xh[obase + (size_t)c * 128 + ci] = h;
        g_xl[obase + (size_t)c * 128 + ci] = __float2half(v - __half2float(h));
    }
}

// ---------------- kernel 4: HMMA conv, cp.async double-buffered ----------------
#define A_PITCH 40
#define A_TILE  (128 * A_PITCH)       // 5120 halves per kw
#define A_BUF   (3 * A_TILE)          // 15360
#define B_ROW   (66 * A_PITCH)        // 2640 halves per (hl,rr)
#define B_BUF   (4 * B_ROW)           // 10560
#define SMEM_BYTES ((2 * A_BUF + 2 * B_BUF) * 2)   // 103680

__global__ void __launch_bounds__(256, 2) conv_mma_kernel(float* __restrict__ y) {
    extern __shared__ __half sm[];
    const uint32_t as0 = smem_u32(sm);
    const uint32_t as1 = as0 + A_BUF * 2;
    const uint32_t bs0 = as0 + 2 * A_BUF * 2;
    const uint32_t bs1 = bs0 + B_BUF * 2;

    const int t = threadIdx.x, lane = t & 31, w = t >> 5;
    const int b = blockIdx.y, q = blockIdx.x;
    const int cog = w >> 2, posg = w & 3;
    const int rr_w = posg >> 1, c0w = (posg & 1) * 32;

    const int a_mrow = lane & 15;
    const int a_koff = (lane >= 16) ? 8 : 0;
    const int b_nrow = (lane & 7) + ((lane >= 16) ? 8 : 0);
    const int b_koff = ((lane >> 3) & 1) * 8;

    float acc[4][4][4];
#pragma unroll
    for (int mf = 0; mf < 4; mf++)
#pragma unroll
        for (int nf = 0; nf < 4; nf++)
#pragma unroll
            for (int e = 0; e < 4; e++) acc[mf][nf][e] = 0.f;

    // ---- staging (cp.async) ----
    auto stage = [&](uint32_t as_b, uint32_t bs_b, int kh, int cch) {
        // A: 3 kw x 128 co x 32 ci -> 1536 x 16B
#pragma unroll
        for (int i = 0; i < 6; i++) {
            const int idx = t + i * 256;
            const int u = idx & 3, co = (idx >> 2) & 127, kw = idx >> 9;
            const __half* src = g_k +
                ((size_t)(b * 9 + kh * 3 + kw) * 16384 + (size_t)co * 128 + cch * 32 + u * 8);
            cpa16(as_b + (uint32_t)(kw * A_TILE + co * A_PITCH + u * 8) * 2, src);
        }
        // B: 2 hl x 2 rr x 66 pc x 32 ci -> 1056 x 16B
#pragma unroll
        for (int i = 0; i < 5; i++) {
            const int idx = t + i * 256;
            if (idx < 1056) {
                const int u = idx & 3;
                const int pcr = idx >> 2;          // 0..263
                const int pc = pcr % 66, rrhl = pcr / 66;   // rrhl in 0..3
                const int rr = rrhl & 1, hl = rrhl >> 1;
                const __half* src = (hl ? g_xl : g_xh) +
                    (((size_t)b * 66 + (q * 2 + rr + kh)) * 66 + pc) * 128 + cch * 32 + u * 8;
                cpa16(bs_b + (uint32_t)(rrhl * B_ROW + pc * A_PITCH + u * 8) * 2, src);
            }
        }
    };

    stage(as0, bs0, 0, 0);
    asm volatile("cp.async.commit_group;" ::: "memory");

#pragma unroll 1
    for (int s = 0; s < 12; s++) {
        const int buf = s & 1;
        if (s < 11) {
            const int sn = s + 1;
            stage(buf ? as0 : as1, buf ? bs0 : bs1, sn >> 2, sn & 3);
            asm volatile("cp.async.commit_group;" ::: "memory");
            asm volatile("cp.async.wait_group 1;" ::: "memory");
        } else {
            asm volatile("cp.async.wait_group 0;" ::: "memory");
        }
        __syncthreads();

        const uint32_t as_b = buf ? as1 : as0;
        const uint32_t bs_b = buf ? bs1 : bs0;
#pragma unroll
        for (int kw = 0; kw < 3; kw++) {
#pragma unroll
            for (int k16 = 0; k16 < 2; k16++) {
                const int k0 = k16 * 16;
                uint32_t Bh[8], Bl[8];
#pragma unroll
                for (int p = 0; p < 2; p++) {
                    const uint32_t ad = bs_b +
                        (uint32_t)(rr_w * B_ROW + (c0w + p * 16 + b_nrow + kw) * A_PITCH + k0 + b_koff) * 2;
                    ldm4(&Bh[p * 4], ad);
                    ldm4(&Bl[p * 4], ad + 2 * B_ROW * 2);
                }
#pragma unroll
                for (int mf = 0; mf < 4; mf++) {
                    uint32_t Ah[4];
                    const uint32_t aa = as_b +
                        (uint32_t)(kw * A_TILE + (cog * 64 + mf * 16 + a_mrow) * A_PITCH + k0 + a_koff) * 2;
                    ldm4(Ah, aa);
#pragma unroll
                    for (int nf = 0; nf < 4; nf++) {
                        const int bi = (nf >> 1) * 4 + (nf & 1) * 2;
                        mma16816(acc[mf][nf], Ah, Bh[bi], Bh[bi + 1]);
                        mma16816(acc[mf][nf], Ah, Bl[bi], Bl[bi + 1]);
                    }
                }
            }
        }
        __syncthreads();
    }

    // ---- epilogue: add generated bias, store fp32 ----
    const int row_g = q * 2 + rr_w;
#pragma unroll
    for (int mf = 0; mf < 4; mf++) {
        const int co_a = cog * 64 + mf * 16 + (lane >> 2);
        const float bv0 = g_ks[(size_t)b * JTOT + KSZ + co_a];
        const float bv1 = g_ks[(size_t)b * JTOT + KSZ + co_a + 8];
        float* base0 = y + (((size_t)b * 128 + co_a) * 64 + row_g) * 64;
        float* base1 = y + (((size_t)b * 128 + co_a + 8) * 64 + row_g) * 64;
#pragma unroll
        for (int nf = 0; nf < 4; nf++) {
            const int col = c0w + nf * 8 + (lane & 3) * 2;
            float2 v0 = make_float2(acc[mf][nf][0] + bv0, acc[mf][nf][1] + bv0);
            float2 v1 = make_float2(acc[mf][nf][2] + bv1, acc[mf][nf][3] + bv1);
            *reinterpret_cast<float2*>(base0 + col) = v0;
            *reinterpret_cast<float2*>(base1 + col) = v1;
        }
    }
}

// ---------------- launch ----------------
extern "C" void kernel_launch(void* const* d_in, const int* in_sizes, int n_in,
                              void* d_out, int out_size) {
    const float* x    = (const float*)d_in[0];
    const float* lat  = (const float*)d_in[1];
    const float* W    = (const float*)d_in[2];
    const float* bias = (const float*)d_in[3];
    float* y = (float*)d_out;

    cudaFuncSetAttribute(conv_mma_kernel, cudaFuncAttributeMaxDynamicSharedMemorySize, SMEM_BYTES);

    ks_gemm_kernel<<<(JTOT + 511) / 512, 256>>>(lat, W, bias);
    kcvt_kernel<<<(int)(((size_t)B_N * 9 * 128 * 128 + 255) / 256), 256>>>();
    xsplit_kernel<<<dim3(64, B_N), 256>>>(x);
    conv_mma_kernel<<<dim3(32, B_N), 256, SMEM_BYTES>>>(y);
}

// round 9
// speedup vs baseline: 3.1023x; 1.3030x over previous
#include <cuda_runtime.h>
#include <cuda_fp16.h>
#include <cstdint>

#define B_N   16
#define LATD  512
#define KSZ   147456
#define JTOT  147584

typedef unsigned long long ull;

// ---------------- persistent scratch ----------------
__device__ float   g_ks[(size_t)B_N * JTOT];
__device__ __half  g_k [(size_t)B_N * 9 * 128 * 128];   // [b][tap][co][ci] fp16
__device__ __half  g_xh[(size_t)B_N * 66 * 66 * 128];   // [b][pr][pc][ci] fp16, zero border

// ---------------- helpers ----------------
__device__ __forceinline__ uint32_t smem_u32(const void* p) {
    uint32_t a;
    asm("{ .reg .u64 t; cvta.to.shared.u64 t, %1; cvt.u32.u64 %0, t; }" : "=r"(a) : "l"(p));
    return a;
}
__device__ __forceinline__ void ldm4(uint32_t* r, uint32_t addr) {
    asm volatile("ldmatrix.sync.aligned.m8n8.x4.shared.b16 {%0,%1,%2,%3}, [%4];"
                 : "=r"(r[0]), "=r"(r[1]), "=r"(r[2]), "=r"(r[3]) : "r"(addr));
}
__device__ __forceinline__ void mma16816(float* c, const uint32_t* a, uint32_t b0, uint32_t b1) {
    asm volatile("mma.sync.aligned.m16n8k16.row.col.f32.f16.f16.f32 "
                 "{%0,%1,%2,%3}, {%4,%5,%6,%7}, {%8,%9}, {%0,%1,%2,%3};"
                 : "+f"(c[0]), "+f"(c[1]), "+f"(c[2]), "+f"(c[3])
                 : "r"(a[0]), "r"(a[1]), "r"(a[2]), "r"(a[3]), "r"(b0), "r"(b1));
}
__device__ __forceinline__ void cpa16(uint32_t d, const void* s) {
    asm volatile("cp.async.ca.shared.global [%0], [%1], 16;" :: "r"(d), "l"(s));
}
__device__ __forceinline__ ull pack2(float lo, float hi) {
    ull r; asm("mov.b64 %0, {%1, %2};" : "=l"(r) : "f"(lo), "f"(hi)); return r;
}
__device__ __forceinline__ void unpack2(ull v, float& lo, float& hi) {
    asm("mov.b64 {%0, %1}, %2;" : "=f"(lo), "=f"(hi) : "l"(v));
}
__device__ __forceinline__ void ffma2(ull& d, ull a, ull b) {
    asm("fma.rn.f32x2 %0, %1, %2, %0;" : "+l"(d) : "l"(a), "l"(b));
}

// ---------------- kernel 1: ks = lat @ W.T + b ----------------
// 128-thread CTA covers 512 j (4 per thread); batch pairs packed f32x2 in smem.
// Per k-step: 8 LDS.64 + 32 FFMA2 -> FFMA2/HBM-bound, not LDS-bound.
__global__ void __launch_bounds__(128) ks_gemm_kernel(const float* __restrict__ lat,
                                                      const float* __restrict__ W,
                                                      const float* __restrict__ bias) {
    __shared__ ull lat2[8 * LATD];   // 32 KB
    const int t = threadIdx.x;
    for (int i = t; i < 8 * LATD; i += 128) {
        const int bp = i >> 9, k = i & 511;
        lat2[i] = pack2(lat[(2 * bp) * LATD + k], lat[(2 * bp + 1) * LATD + k]);
    }
    __syncthreads();

    const int jb = blockIdx.x * 512 + t;
    const float4* Wp[4];
#pragma unroll
    for (int jj = 0; jj < 4; jj++) {
        int j = jb + jj * 128;
        int jc = (j < JTOT) ? j : (JTOT - 1);
        Wp[jj] = reinterpret_cast<const float4*>(W + (size_t)jc * LATD);
    }

    ull acc[4][8];
#pragma unroll
    for (int jj = 0; jj < 4; jj++)
#pragma unroll
        for (int bp = 0; bp < 8; bp++) acc[jj][bp] = 0ULL;

#pragma unroll 2
    for (int kk = 0; kk < LATD / 4; kk++) {
        float4 wv[4];
#pragma unroll
        for (int jj = 0; jj < 4; jj++) wv[jj] = Wp[jj][kk];
#pragma unroll
        for (int e = 0; e < 4; e++) {
            const int k = kk * 4 + e;
            ull l[8];
#pragma unroll
            for (int bp = 0; bp < 8; bp++) l[bp] = lat2[bp * LATD + k];
#pragma unroll
            for (int jj = 0; jj < 4; jj++) {
                const float we = (e == 0) ? wv[jj].x : (e == 1) ? wv[jj].y
                               : (e == 2) ? wv[jj].z : wv[jj].w;
                const ull w = pack2(we, we);
#pragma unroll
                for (int bp = 0; bp < 8; bp++) ffma2(acc[jj][bp], w, l[bp]);
            }
        }
    }

#pragma unroll
    for (int jj = 0; jj < 4; jj++) {
        const int j = jb + jj * 128;
        if (j < JTOT) {
            const float bj = bias[j];
#pragma unroll
            for (int bp = 0; bp < 8; bp++) {
                float lo, hi;
                unpack2(acc[jj][bp], lo, hi);
                g_ks[(size_t)(2 * bp) * JTOT + j]     = lo + bj;
                g_ks[(size_t)(2 * bp + 1) * JTOT + j] = hi + bj;
            }
        }
    }
}

// ---------------- kernel 2: kern -> [b][tap][co][ci] fp16, coalesced both sides ----------------
__global__ void __launch_bounds__(128) kcvt_kernel() {
    __shared__ float s[1152];
    const int b = blockIdx.y, co = blockIdx.x, t = threadIdx.x;
    const float* src = g_ks + (size_t)b * JTOT + (size_t)co * 1152;
    for (int i = t; i < 1152; i += 128) s[i] = src[i];
    __syncthreads();
#pragma unroll
    for (int tap = 0; tap < 9; tap++)
        g_k[(((size_t)b * 9 + tap) * 128 + co) * 128 + t] = __float2half(s[t * 9 + tap]);
}

// ---------------- kernel 3: transpose x -> padded [b][pr][pc][ci] fp16 ----------------
__global__ void __launch_bounds__(256) xsplit_kernel(const float* __restrict__ x) {
    __shared__ float s[128 * 65];
    const int b = blockIdx.y, r = blockIdx.x, t = threadIdx.x;
    const float* xb = x + (size_t)b * 128 * 4096 + (size_t)r * 64;
    for (int i = t; i < 128 * 64; i += 256) {
        int ci = i >> 6, c = i & 63;
        s[ci * 65 + c] = xb[(size_t)ci * 4096 + c];
    }
    __syncthreads();
    size_t obase = ((size_t)b * 66 + (r + 1)) * 66 * 128 + 128;
    for (int i = t; i < 128 * 64; i += 256) {
        int c = i >> 7, ci = i & 127;
        g_xh[obase + (size_t)c * 128 + ci] = __float2half(s[ci * 65 + c]);
    }
}

// ---------------- kernel 4: HMMA conv, single-pass fp16, cp.async double-buffered ----------------
#define A_PITCH 40
#define A_TILE  (128 * A_PITCH)       // 5120 halves per kw
#define A_BUF   (3 * A_TILE)          // 15360
#define B_ROW   (66 * A_PITCH)        // 2640 halves per rr
#define B_BUF   (2 * B_ROW)           // 5280
#define SMEM_BYTES ((2 * A_BUF + 2 * B_BUF) * 2)   // 82560

__global__ void __launch_bounds__(256, 2) conv_mma_kernel(float* __restrict__ y) {
    extern __shared__ __half sm[];
    const uint32_t as0 = smem_u32(sm);
    const uint32_t as1 = as0 + A_BUF * 2;
    const uint32_t bs0 = as0 + 2 * A_BUF * 2;
    const uint32_t bs1 = bs0 + B_BUF * 2;

    const int t = threadIdx.x, lane = t & 31, w = t >> 5;
    const int b = blockIdx.y, q = blockIdx.x;
    const int cog = w >> 2, posg = w & 3;
    const int rr_w = posg >> 1, c0w = (posg & 1) * 32;

    const int a_mrow = lane & 15;
    const int a_koff = (lane >= 16) ? 8 : 0;
    const int b_nrow = (lane & 7) + ((lane >= 16) ? 8 : 0);
    const int b_koff = ((lane >> 3) & 1) * 8;

    float acc[4][4][4];
#pragma unroll
    for (int mf = 0; mf < 4; mf++)
#pragma unroll
        for (int nf = 0; nf < 4; nf++)
#pragma unroll
            for (int e = 0; e < 4; e++) acc[mf][nf][e] = 0.f;

    auto stage = [&](uint32_t as_b, uint32_t bs_b, int kh, int cch) {
        // A: 3 kw x 128 co x 32 ci -> 1536 x 16B
#pragma unroll
        for (int i = 0; i < 6; i++) {
            const int idx = t + i * 256;
            const int u = idx & 3, co = (idx >> 2) & 127, kw = idx >> 9;
            const __half* src = g_k +
                ((size_t)(b * 9 + kh * 3 + kw) * 16384 + (size_t)co * 128 + cch * 32 + u * 8);
            cpa16(as_b + (uint32_t)(kw * A_TILE + co * A_PITCH + u * 8) * 2, src);
        }
        // B: 2 rr x 66 pc x 32 ci -> 528 x 16B
#pragma unroll
        for (int i = 0; i < 3; i++) {
            const int idx = t + i * 256;
            if (idx < 528) {
                const int u = idx & 3;
                const int pcr = idx >> 2;              // 0..131
                const int pc = pcr % 66, rr = pcr / 66;
                const __half* src = g_xh +
                    (((size_t)b * 66 + (q * 2 + rr + kh)) * 66 + pc) * 128 + cch * 32 + u * 8;
                cpa16(bs_b + (uint32_t)(rr * B_ROW + pc * A_PITCH + u * 8) * 2, src);
            }
        }
    };

    stage(as0, bs0, 0, 0);
    asm volatile("cp.async.commit_group;" ::: "memory");

#pragma unroll 1
    for (int s = 0; s < 12; s++) {
        const int buf = s & 1;
        if (s < 11) {
            const int sn = s + 1;
            stage(buf ? as0 : as1, buf ? bs0 : bs1, sn >> 2, sn & 3);
            asm volatile("cp.async.commit_group;" ::: "memory");
            asm volatile("cp.async.wait_group 1;" ::: "memory");
        } else {
            asm volatile("cp.async.wait_group 0;" ::: "memory");
        }
        __syncthreads();

        const uint32_t as_b = buf ? as1 : as0;
        const uint32_t bs_b = buf ? bs1 : bs0;
#pragma unroll
        for (int kw = 0; kw < 3; kw++) {
#pragma unroll
            for (int k16 = 0; k16 < 2; k16++) {
                const int k0 = k16 * 16;
                uint32_t Bh[8];
#pragma unroll
                for (int p = 0; p < 2; p++) {
                    const uint32_t ad = bs_b +
                        (uint32_t)(rr_w * B_ROW + (c0w + p * 16 + b_nrow + kw) * A_PITCH + k0 + b_koff) * 2;
                    ldm4(&Bh[p * 4], ad);
                }
#pragma unroll
                for (int mf = 0; mf < 4; mf++) {
                    uint32_t Ah[4];
                    const uint32_t aa = as_b +
                        (uint32_t)(kw * A_TILE + (cog * 64 + mf * 16 + a_mrow) * A_PITCH + k0 + a_koff) * 2;
                    ldm4(Ah, aa);
#pragma unroll
                    for (int nf = 0; nf < 4; nf++) {
                        const int bi = (nf >> 1) * 4 + (nf & 1) * 2;
                        mma16816(acc[mf][nf], Ah, Bh[bi], Bh[bi + 1]);
                    }
                }
            }
        }
        __syncthreads();
    }

    // ---- epilogue: add generated bias, store fp32 ----
    const int row_g = q * 2 + rr_w;
#pragma unroll
    for (int mf = 0; mf < 4; mf++) {
        const int co_a = cog * 64 + mf * 16 + (lane >> 2);
        const float bv0 = g_ks[(size_t)b * JTOT + KSZ + co_a];
        const float bv1 = g_ks[(size_t)b * JTOT + KSZ + co_a + 8];
        float* base0 = y + (((size_t)b * 128 + co_a) * 64 + row_g) * 64;
        float* base1 = y + (((size_t)b * 128 + co_a + 8) * 64 + row_g) * 64;
#pragma unroll
        for (int nf = 0; nf < 4; nf++) {
            const int col = c0w + nf * 8 + (lane & 3) * 2;
            float2 v0 = make_float2(acc[mf][nf][0] + bv0, acc[mf][nf][1] + bv0);
            float2 v1 = make_float2(acc[mf][nf][2] + bv1, acc[mf][nf][3] + bv1);
            *reinterpret_cast<float2*>(base0 + col) = v0;
            *reinterpret_cast<float2*>(base1 + col) = v1;
        }
    }
}

// ---------------- launch ----------------
extern "C" void kernel_launch(void* const* d_in, const int* in_sizes, int n_in,
                              void* d_out, int out_size) {
    const float* x    = (const float*)d_in[0];
    const float* lat  = (const float*)d_in[1];
    const float* W    = (const float*)d_in[2];
    const float* bias = (const float*)d_in[3];
    float* y = (float*)d_out;

    cudaFuncSetAttribute(conv_mma_kernel, cudaFuncAttributeMaxDynamicSharedMemorySize, SMEM_BYTES);

    ks_gemm_kernel<<<(JTOT + 511) / 512, 128>>>(lat, W, bias);
    kcvt_kernel<<<dim3(128, B_N), 128>>>();
    xsplit_kernel<<<dim3(64, B_N), 256>>>(x);
    conv_mma_kernel<<<dim3(32, B_N), 256, SMEM_BYTES>>>(y);
}

// round 10
// speedup vs baseline: 3.1854x; 1.0268x over previous
#include <cuda_runtime.h>
#include <cuda_fp16.h>
#include <cstdint>

#define B_N   16
#define LATD  512
#define KSZ   147456
#define JTOT  147584

typedef unsigned long long ull;

// ---------------- persistent scratch ----------------
__device__ float   g_ks[(size_t)B_N * JTOT];
__device__ __half  g_k [(size_t)B_N * 9 * 128 * 128];   // [b][tap][co][ci] fp16
__device__ __half  g_xh[(size_t)B_N * 66 * 66 * 128];   // [b][pr][pc][ci] fp16, zero border

// ---------------- helpers ----------------
__device__ __forceinline__ uint32_t smem_u32(const void* p) {
    uint32_t a;
    asm("{ .reg .u64 t; cvta.to.shared.u64 t, %1; cvt.u32.u64 %0, t; }" : "=r"(a) : "l"(p));
    return a;
}
__device__ __forceinline__ void ldm4(uint32_t* r, uint32_t addr) {
    asm volatile("ldmatrix.sync.aligned.m8n8.x4.shared.b16 {%0,%1,%2,%3}, [%4];"
                 : "=r"(r[0]), "=r"(r[1]), "=r"(r[2]), "=r"(r[3]) : "r"(addr));
}
__device__ __forceinline__ void mma16816(float* c, const uint32_t* a, uint32_t b0, uint32_t b1) {
    asm volatile("mma.sync.aligned.m16n8k16.row.col.f32.f16.f16.f32 "
                 "{%0,%1,%2,%3}, {%4,%5,%6,%7}, {%8,%9}, {%0,%1,%2,%3};"
                 : "+f"(c[0]), "+f"(c[1]), "+f"(c[2]), "+f"(c[3])
                 : "r"(a[0]), "r"(a[1]), "r"(a[2]), "r"(a[3]), "r"(b0), "r"(b1));
}
__device__ __forceinline__ void cpa16(uint32_t d, const void* s) {
    asm volatile("cp.async.ca.shared.global [%0], [%1], 16;" :: "r"(d), "l"(s));
}
// packed cvt: d = {lo = cvt(lo), hi = cvt(hi)}
__device__ __forceinline__ uint32_t cvt2h(float lo, float hi) {
    uint32_t d;
    asm("cvt.rn.f16x2.f32 %0, %1, %2;" : "=r"(d) : "f"(hi), "f"(lo));
    return d;
}

// ---------------- kernel 1: ks = lat @ W.T + b  (HMMA, DRAM-streaming-bound) ----------------
// m16n8k16: B fragment = (W[j][k], W[j][k+1]) per lane -> direct float2 global loads + cvt.
// A (lat) split fp16 hi/lo, per-lane fragments precomputed into smem once per CTA.
// Warp = one j8 block; CTA = 8 warps = 64 j; grid = 18448/8 = 2306.
__global__ void __launch_bounds__(256) ks_mma_kernel(const float* __restrict__ lat,
                                                     const float* __restrict__ W,
                                                     const float* __restrict__ bias) {
    __shared__ uint32_t afrag[2][32][32][4];   // [hl][ktile][lane][reg] = 32 KB
    const int t = threadIdx.x, lane = t & 31, w = t >> 5;

    // ---- precompute A fragments (each warp does 4 k-tiles) ----
    {
        const int m = lane >> 2, kq = (lane & 3) * 2;
#pragma unroll
        for (int i = 0; i < 4; i++) {
            const int kt = w * 4 + i;
            const int k0 = kt * 16 + kq;
            // reg r: (row, cols): r0=(m,k0,k0+1) r1=(m+8,..) r2=(m,k0+8,k0+9) r3=(m+8,k0+8..)
            const float v[8] = {
                lat[m * LATD + k0],       lat[m * LATD + k0 + 1],
                lat[(m + 8) * LATD + k0], lat[(m + 8) * LATD + k0 + 1],
                lat[m * LATD + k0 + 8],       lat[m * LATD + k0 + 9],
                lat[(m + 8) * LATD + k0 + 8], lat[(m + 8) * LATD + k0 + 9]
            };
#pragma unroll
            for (int r = 0; r < 4; r++) {
                const float lo = v[2 * r], hi = v[2 * r + 1];
                const uint32_t hfrag = cvt2h(lo, hi);
                afrag[0][kt][lane][r] = hfrag;
                const __half2 hv = *reinterpret_cast<const __half2*>(&hfrag);
                afrag[1][kt][lane][r] = cvt2h(lo - __low2float(hv), hi - __high2float(hv));
            }
        }
    }
    __syncthreads();

    // ---- main: warp handles j8 block; B fragments straight from global W ----
    const int jb = (blockIdx.x * 8 + w) * 8;
    const int j_row = jb + (lane >> 2);                 // this lane's W row (n)
    const float* Wb = W + (size_t)j_row * LATD + (lane & 3) * 2;

    float acc[4] = {0.f, 0.f, 0.f, 0.f};
#pragma unroll 4
    for (int kt = 0; kt < 32; kt++) {
        const float2 w0 = *reinterpret_cast<const float2*>(Wb + kt * 16);
        const float2 w1 = *reinterpret_cast<const float2*>(Wb + kt * 16 + 8);
        const uint32_t b0 = cvt2h(w0.x, w0.y);
        const uint32_t b1 = cvt2h(w1.x, w1.y);
        const uint4 Ah = *reinterpret_cast<const uint4*>(&afrag[0][kt][lane][0]);
        const uint4 Al = *reinterpret_cast<const uint4*>(&afrag[1][kt][lane][0]);
        mma16816(acc, reinterpret_cast<const uint32_t*>(&Ah), b0, b1);
        mma16816(acc, reinterpret_cast<const uint32_t*>(&Al), b0, b1);
    }

    // ---- epilogue: add bias, write g_ks (c0,c1: batch=lane>>2; c2,c3: batch+8) ----
    const int j0 = jb + (lane & 3) * 2;
    const float2 bs = *reinterpret_cast<const float2*>(bias + j0);
    const int br = lane >> 2;
    float2 o0 = make_float2(acc[0] + bs.x, acc[1] + bs.y);
    float2 o1 = make_float2(acc[2] + bs.x, acc[3] + bs.y);
    *reinterpret_cast<float2*>(g_ks + (size_t)br * JTOT + j0)       = o0;
    *reinterpret_cast<float2*>(g_ks + (size_t)(br + 8) * JTOT + j0) = o1;
}

// ---------------- kernel 2: kern -> [b][tap][co][ci] fp16, coalesced both sides ----------------
__global__ void __launch_bounds__(128) kcvt_kernel() {
    __shared__ float s[1152];
    const int b = blockIdx.y, co = blockIdx.x, t = threadIdx.x;
    const float* src = g_ks + (size_t)b * JTOT + (size_t)co * 1152;
    for (int i = t; i < 1152; i += 128) s[i] = src[i];
    __syncthreads();
#pragma unroll
    for (int tap = 0; tap < 9; tap++)
        g_k[(((size_t)b * 9 + tap) * 128 + co) * 128 + t] = __float2half(s[t * 9 + tap]);
}

// ---------------- kernel 3: transpose x -> padded [b][pr][pc][ci] fp16 ----------------
__global__ void __launch_bounds__(256) xsplit_kernel(const float* __restrict__ x) {
    __shared__ float s[128 * 65];
    const int b = blockIdx.y, r = blockIdx.x, t = threadIdx.x;
    const float* xb = x + (size_t)b * 128 * 4096 + (size_t)r * 64;
    for (int i = t; i < 128 * 64; i += 256) {
        int ci = i >> 6, c = i & 63;
        s[ci * 65 + c] = xb[(size_t)ci * 4096 + c];
    }
    __syncthreads();
    size_t obase = ((size_t)b * 66 + (r + 1)) * 66 * 128 + 128;
    for (int i = t; i < 128 * 64; i += 256) {
        int c = i >> 7, ci = i & 127;
        g_xh[obase + (size_t)c * 128 + ci] = __float2half(s[ci * 65 + c]);
    }
}

// ---------------- kernel 4: HMMA conv, single-pass fp16, cp.async double-buffered ----------------
#define A_PITCH 40
#define A_TILE  (128 * A_PITCH)
#define A_BUF   (3 * A_TILE)
#define B_ROW   (66 * A_PITCH)
#define B_BUF   (2 * B_ROW)
#define SMEM_BYTES ((2 * A_BUF + 2 * B_BUF) * 2)   // 82560

__global__ void __launch_bounds__(256, 2) conv_mma_kernel(float* __restrict__ y) {
    extern __shared__ __half sm[];
    const uint32_t as0 = smem_u32(sm);
    const uint32_t as1 = as0 + A_BUF * 2;
    const uint32_t bs0 = as0 + 2 * A_BUF * 2;
    const uint32_t bs1 = bs0 + B_BUF * 2;

    const int t = threadIdx.x, lane = t & 31, w = t >> 5;
    const int b = blockIdx.y, q = blockIdx.x;
    const int cog = w >> 2, posg = w & 3;
    const int rr_w = posg >> 1, c0w = (posg & 1) * 32;

    const int a_mrow = lane & 15;
    const int a_koff = (lane >= 16) ? 8 : 0;
    const int b_nrow = (lane & 7) + ((lane >= 16) ? 8 : 0);
    const int b_koff = ((lane >> 3) & 1) * 8;

    float acc[4][4][4];
#pragma unroll
    for (int mf = 0; mf < 4; mf++)
#pragma unroll
        for (int nf = 0; nf < 4; nf++)
#pragma unroll
            for (int e = 0; e < 4; e++) acc[mf][nf][e] = 0.f;

    auto stage = [&](uint32_t as_b, uint32_t bs_b, int kh, int cch) {
#pragma unroll
        for (int i = 0; i < 6; i++) {
            const int idx = t + i * 256;
            const int u = idx & 3, co = (idx >> 2) & 127, kw = idx >> 9;
            const __half* src = g_k +
                ((size_t)(b * 9 + kh * 3 + kw) * 16384 + (size_t)co * 128 + cch * 32 + u * 8);
            cpa16(as_b + (uint32_t)(kw * A_TILE + co * A_PITCH + u * 8) * 2, src);
        }
#pragma unroll
        for (int i = 0; i < 3; i++) {
            const int idx = t + i * 256;
            if (idx < 528) {
                const int u = idx & 3;
                const int pcr = idx >> 2;
                const int pc = pcr % 66, rr = pcr / 66;
                const __half* src = g_xh +
                    (((size_t)b * 66 + (q * 2 + rr + kh)) * 66 + pc) * 128 + cch * 32 + u * 8;
                cpa16(bs_b + (uint32_t)(rr * B_ROW + pc * A_PITCH + u * 8) * 2, src);
            }
        }
    };

    stage(as0, bs0, 0, 0);
    asm volatile("cp.async.commit_group;" ::: "memory");

#pragma unroll 1
    for (int s = 0; s < 12; s++) {
        const int buf = s & 1;
        if (s < 11) {
            const int sn = s + 1;
            stage(buf ? as0 : as1, buf ? bs0 : bs1, sn >> 2, sn & 3);
            asm volatile("cp.async.commit_group;" ::: "memory");
            asm volatile("cp.async.wait_group 1;" ::: "memory");
        } else {
            asm volatile("cp.async.wait_group 0;" ::: "memory");
        }
        __syncthreads();

        const uint32_t as_b = buf ? as1 : as0;
        const uint32_t bs_b = buf ? bs1 : bs0;
#pragma unroll
        for (int kw = 0; kw < 3; kw++) {
#pragma unroll
            for (int k16 = 0; k16 < 2; k16++) {
                const int k0 = k16 * 16;
                uint32_t Bh[8];
#pragma unroll
                for (int p = 0; p < 2; p++) {
                    const uint32_t ad = bs_b +
                        (uint32_t)(rr_w * B_ROW + (c0w + p * 16 + b_nrow + kw) * A_PITCH + k0 + b_koff) * 2;
                    ldm4(&Bh[p * 4], ad);
                }
#pragma unroll
                for (int mf = 0; mf < 4; mf++) {
                    uint32_t Ah[4];
                    const uint32_t aa = as_b +
                        (uint32_t)(kw * A_TILE + (cog * 64 + mf * 16 + a_mrow) * A_PITCH + k0 + a_koff) * 2;
                    ldm4(Ah, aa);
#pragma unroll
                    for (int nf = 0; nf < 4; nf++) {
                        const int bi = (nf >> 1) * 4 + (nf & 1) * 2;
                        mma16816(acc[mf][nf], Ah, Bh[bi], Bh[bi + 1]);
                    }
                }
            }
        }
        __syncthreads();
    }

    const int row_g = q * 2 + rr_w;
#pragma unroll
    for (int mf = 0; mf < 4; mf++) {
        const int co_a = cog * 64 + mf * 16 + (lane >> 2);
        const float bv0 = g_ks[(size_t)b * JTOT + KSZ + co_a];
        const float bv1 = g_ks[(size_t)b * JTOT + KSZ + co_a + 8];
        float* base0 = y + (((size_t)b * 128 + co_a) * 64 + row_g) * 64;
        float* base1 = y + (((size_t)b * 128 + co_a + 8) * 64 + row_g) * 64;
#pragma unroll
        for (int nf = 0; nf < 4; nf++) {
            const int col = c0w + nf * 8 + (lane & 3) * 2;
            float2 v0 = make_float2(acc[mf][nf][0] + bv0, acc[mf][nf][1] + bv0);
            float2 v1 = make_float2(acc[mf][nf][2] + bv1, acc[mf][nf][3] + bv1);
            *reinterpret_cast<float2*>(base0 + col) = v0;
            *reinterpret_cast<float2*>(base1 + col) = v1;
        }
    }
}

// ---------------- launch ----------------
extern "C" void kernel_launch(void* const* d_in, const int* in_sizes, int n_in,
                              void* d_out, int out_size) {
    const float* x    = (const float*)d_in[0];
    const float* lat  = (const float*)d_in[1];
    const float* W    = (const float*)d_in[2];
    const float* bias = (const float*)d_in[3];
    float* y = (float*)d_out;

    cudaFuncSetAttribute(conv_mma_kernel, cudaFuncAttributeMaxDynamicSharedMemorySize, SMEM_BYTES);

    ks_mma_kernel<<<JTOT / 64, 256>>>(lat, W, bias);     // 2306 CTAs
    kcvt_kernel<<<dim3(128, B_N), 128>>>();
    xsplit_kernel<<<dim3(64, B_N), 256>>>(x);
    conv_mma_kernel<<<dim3(32, B_N), 256, SMEM_BYTES>>>(y);
}